// round 9
// baseline (speedup 1.0000x reference)
#include <cuda_runtime.h>
#include <cuda_bf16.h>
#include <math.h>

#define Nn 20000
#define HID 256
#define ZD 64
#define E2 240000     // directed encoder edges (2E)
#define EP 120000     // positive edges
#define EN 600000     // negative edges
#define ET 720000     // EP+EN
#define NT64 (ET / 64)     // 11250 tiles of 64 edges
#define CAP 96             // max in-degree bucket (avg 12, Poisson tail ~0)

typedef unsigned long long ull;
typedef unsigned int uint32;

// ---------------- helpers ----------------
__device__ __forceinline__ ull splat2(float v) {
    ull r; asm("mov.b64 %0, {%1, %1};" : "=l"(r) : "f"(v)); return r;
}
__device__ __forceinline__ ull fma2(ull a, ull b, ull c) {
    ull d; asm("fma.rn.f32x2 %0, %1, %2, %3;" : "=l"(d) : "l"(a), "l"(b), "l"(c)); return d;
}
__device__ __forceinline__ float2 unpack2(ull v) {
    float2 f; asm("mov.b64 {%0, %1}, %2;" : "=f"(f.x), "=f"(f.y) : "l"(v)); return f;
}
__device__ __forceinline__ uint32 bfp2(float lo, float hi) {
    uint32 r; asm("cvt.rn.bf16x2.f32 %0, %1, %2;" : "=r"(r) : "f"(hi), "f"(lo)); return r;
}
__device__ __forceinline__ uint32 smem_u32(const void* p) {
    uint32 a; asm("{ .reg .u64 t; cvta.to.shared.u64 t, %1; cvt.u32.u64 %0, t; }" : "=r"(a) : "l"(p));
    return a;
}
__device__ __forceinline__ void ldsm4(uint32* r, uint32 addr) {
    asm volatile("ldmatrix.sync.aligned.m8n8.x4.shared.b16 {%0,%1,%2,%3}, [%4];"
        : "=r"(r[0]), "=r"(r[1]), "=r"(r[2]), "=r"(r[3]) : "r"(addr));
}
__device__ __forceinline__ void mma16816(float* c, const uint32* a, uint32 b0, uint32 b1) {
    asm volatile("mma.sync.aligned.m16n8k16.row.col.f32.bf16.bf16.f32 "
        "{%0,%1,%2,%3}, {%4,%5,%6,%7}, {%8,%9}, {%0,%1,%2,%3};"
        : "+f"(c[0]), "+f"(c[1]), "+f"(c[2]), "+f"(c[3])
        : "r"(a[0]), "r"(a[1]), "r"(a[2]), "r"(a[3]), "r"(b0), "r"(b1));
}

// ---------------- scratch ----------------
__device__ float g_m1[Nn * HID];        // x@W1, then decoder msg reuse
__device__ float g_h1[Nn * HID];        // encoder hidden
__device__ float g_mlv[Nn * 128];       // [mu_m | lv_m] pre-gather
__device__ float g_z[Nn * ZD];
__device__ float g_dm[Nn * ZD];
__device__ float g_hA[Nn * ZD];
__device__ float g_hB[Nn * ZD];
__device__ float g_dis[Nn];
__device__ int   g_degE[Nn];
__device__ int   g_degD[Nn];
__device__ int   g_epermv[Nn * CAP];
__device__ int   g_dpermv[Nn * CAP];
__device__ double g_acc[2];

// ---------------- init + CSR fill ----------------
__global__ void zero_k() {
    int i = blockIdx.x * blockDim.x + threadIdx.x;
    if (i < Nn) { g_degE[i] = 0; g_degD[i] = 0; }
    if (i < 2) g_acc[i] = 0.0;
}
__global__ void fill_k(const int* __restrict__ src, const int* __restrict__ dst,
                       int n, int* __restrict__ perm, int* __restrict__ deg)
{
    int e = blockIdx.x * blockDim.x + threadIdx.x;
    if (e >= n) return;
    int d = dst[e];
    int slot = atomicAdd(&deg[d], 1);
    if (slot < CAP) perm[d * CAP + slot] = src[e];
}
__global__ void dis_k() {
    int n = blockIdx.x * blockDim.x + threadIdx.x;
    if (n < Nn) g_dis[n] = rsqrtf((float)min(g_degD[n], CAP) + 1.0f);
}

// ---------------- tiled fp32 GEMM with FFMA2 ----------------
__global__ void gemm_k(const float* __restrict__ A, const float* __restrict__ B,
                       float* __restrict__ C, int M, int Ncols, int K,
                       int lda, int ldb, int ldc)
{
    __shared__ float As[16][64];
    __shared__ float Bs[16][64];
    int tid = threadIdx.x;
    int tx = tid & 15, ty = tid >> 4;
    int bm0 = blockIdx.y * 64, bn0 = blockIdx.x * 64;

    ull pacc[4][2];
    #pragma unroll
    for (int i = 0; i < 4; i++) { pacc[i][0] = 0ull; pacc[i][1] = 0ull; }

    for (int k0 = 0; k0 < K; k0 += 16) {
        {
            int r = tid >> 2, kk = (tid & 3) << 2;
            float4 v = make_float4(0.f, 0.f, 0.f, 0.f);
            if (bm0 + r < M)
                v = *(const float4*)(A + (size_t)(bm0 + r) * lda + k0 + kk);
            As[kk + 0][r] = v.x; As[kk + 1][r] = v.y;
            As[kk + 2][r] = v.z; As[kk + 3][r] = v.w;
        }
        {
            int kk = tid >> 4, c = (tid & 15) << 2;
            float4 v = *(const float4*)(B + (size_t)(k0 + kk) * ldb + bn0 + c);
            *(float4*)&Bs[kk][c] = v;
        }
        __syncthreads();
        #pragma unroll
        for (int kk = 0; kk < 16; kk++) {
            float4 a = *(const float4*)&As[kk][ty * 4];
            const ull* bp = (const ull*)&Bs[kk][tx * 4];
            ull b01 = bp[0], b23 = bp[1];
            float av[4] = {a.x, a.y, a.z, a.w};
            #pragma unroll
            for (int i = 0; i < 4; i++) {
                ull as = splat2(av[i]);
                pacc[i][0] = fma2(b01, as, pacc[i][0]);
                pacc[i][1] = fma2(b23, as, pacc[i][1]);
            }
        }
        __syncthreads();
    }
    #pragma unroll
    for (int i = 0; i < 4; i++) {
        int row = bm0 + ty * 4 + i;
        if (row < M) {
            float2 lo = unpack2(pacc[i][0]);
            float2 hi = unpack2(pacc[i][1]);
            *(float4*)(C + (size_t)row * ldc + bn0 + tx * 4) =
                make_float4(lo.x, lo.y, hi.x, hi.y);
        }
    }
}

// ---------------- encoder gather + bias + LayerNorm + ReLU ----------------
// warp per node, lane covers cols [8L, 8L+8)
__global__ void enc_gather_ln_k(const float* __restrict__ b1, const float* __restrict__ g1,
                                const float* __restrict__ bt1)
{
    int row = blockIdx.x * (blockDim.x >> 5) + (threadIdx.x >> 5);
    int lane = threadIdx.x & 31;
    if (row >= Nn) return;
    int dg = min(g_degE[row], CAP);
    const int* pp = &g_epermv[row * CAP];
    float4 a0 = make_float4(0.f, 0.f, 0.f, 0.f);
    float4 a1 = make_float4(0.f, 0.f, 0.f, 0.f);
    for (int i = 0; i < dg; i++) {
        int s = pp[i];
        const float4* m = (const float4*)&g_m1[(size_t)s * 256 + lane * 8];
        float4 v0 = m[0], v1 = m[1];
        a0.x += v0.x; a0.y += v0.y; a0.z += v0.z; a0.w += v0.w;
        a1.x += v1.x; a1.y += v1.y; a1.z += v1.z; a1.w += v1.w;
    }
    float v[8];
    const float4* bb0 = (const float4*)&b1[lane * 8];
    float4 b0 = bb0[0], b1v = bb0[1];
    v[0] = a0.x + b0.x;  v[1] = a0.y + b0.y;  v[2] = a0.z + b0.z;  v[3] = a0.w + b0.w;
    v[4] = a1.x + b1v.x; v[5] = a1.y + b1v.y; v[6] = a1.z + b1v.z; v[7] = a1.w + b1v.w;
    float s = 0.f;
    #pragma unroll
    for (int i = 0; i < 8; i++) s += v[i];
    #pragma unroll
    for (int o = 16; o; o >>= 1) s += __shfl_xor_sync(0xffffffffu, s, o);
    float mu = s * (1.0f / 256.0f);
    float vs = 0.f;
    #pragma unroll
    for (int i = 0; i < 8; i++) { float d = v[i] - mu; vs += d * d; }
    #pragma unroll
    for (int o = 16; o; o >>= 1) vs += __shfl_xor_sync(0xffffffffu, vs, o);
    float rs = rsqrtf(vs * (1.0f / 256.0f) + 1e-5f);
    const float4* gg = (const float4*)&g1[lane * 8];
    const float4* bt = (const float4*)&bt1[lane * 8];
    float4 g0 = gg[0], g1x = gg[1], t0 = bt[0], t1 = bt[1];
    float4 o0, o1;
    o0.x = fmaxf((v[0] - mu) * rs * g0.x + t0.x, 0.f);
    o0.y = fmaxf((v[1] - mu) * rs * g0.y + t0.y, 0.f);
    o0.z = fmaxf((v[2] - mu) * rs * g0.z + t0.z, 0.f);
    o0.w = fmaxf((v[3] - mu) * rs * g0.w + t0.w, 0.f);
    o1.x = fmaxf((v[4] - mu) * rs * g1x.x + t1.x, 0.f);
    o1.y = fmaxf((v[5] - mu) * rs * g1x.y + t1.y, 0.f);
    o1.z = fmaxf((v[6] - mu) * rs * g1x.z + t1.z, 0.f);
    o1.w = fmaxf((v[7] - mu) * rs * g1x.w + t1.w, 0.f);
    float4* outp = (float4*)&g_h1[(size_t)row * 256 + lane * 8];
    outp[0] = o0; outp[1] = o1;
}

// ---------------- mu/lv gather + bias + z + KL ----------------
// warp per node, lane covers cols [4L, 4L+4) of 128-wide [mu|lv] row
__global__ void mulv_gather_zkl_k(const float* __restrict__ eps,
                                  const float* __restrict__ bmu,
                                  const float* __restrict__ blv)
{
    __shared__ float kred[8];
    int wip = threadIdx.x >> 5;
    int row = blockIdx.x * (blockDim.x >> 5) + wip;
    int lane = threadIdx.x & 31;
    float kl = 0.f;
    if (row < Nn) {
        int dg = min(g_degE[row], CAP);
        const int* pp = &g_epermv[row * CAP];
        float4 acc = make_float4(0.f, 0.f, 0.f, 0.f);
        for (int i = 0; i < dg; i++) {
            int s = pp[i];
            float4 v = *(const float4*)&g_mlv[(size_t)s * 128 + lane * 4];
            acc.x += v.x; acc.y += v.y; acc.z += v.z; acc.w += v.w;
        }
        // add bias: lanes 0-15 are mu cols, 16-31 are lv cols
        float4 bias = (lane < 16) ? *(const float4*)&bmu[lane * 4]
                                  : *(const float4*)&blv[(lane - 16) * 4];
        acc.x += bias.x; acc.y += bias.y; acc.z += bias.z; acc.w += bias.w;
        // pair: lane < 16 pulls lv from lane+16
        float lv0 = __shfl_sync(0xffffffffu, acc.x, lane + 16);
        float lv1 = __shfl_sync(0xffffffffu, acc.y, lane + 16);
        float lv2 = __shfl_sync(0xffffffffu, acc.z, lane + 16);
        float lv3 = __shfl_sync(0xffffffffu, acc.w, lane + 16);
        if (lane < 16) {
            float4 ev = *(const float4*)&eps[(size_t)row * 64 + lane * 4];
            float4 zv;
            zv.x = acc.x + ev.x * expf(0.5f * lv0);
            zv.y = acc.y + ev.y * expf(0.5f * lv1);
            zv.z = acc.z + ev.z * expf(0.5f * lv2);
            zv.w = acc.w + ev.w * expf(0.5f * lv3);
            *(float4*)&g_z[(size_t)row * 64 + lane * 4] = zv;
            kl += 1.0f + lv0 - acc.x * acc.x - expf(lv0);
            kl += 1.0f + lv1 - acc.y * acc.y - expf(lv1);
            kl += 1.0f + lv2 - acc.z * acc.z - expf(lv2);
            kl += 1.0f + lv3 - acc.w * acc.w - expf(lv3);
        }
    }
    #pragma unroll
    for (int o = 16; o; o >>= 1) kl += __shfl_xor_sync(0xffffffffu, kl, o);
    if (lane == 0) kred[wip] = kl;
    __syncthreads();
    if (threadIdx.x == 0) {
        float t = 0.f;
        #pragma unroll
        for (int w = 0; w < 8; w++) t += kred[w];
        atomicAdd(&g_acc[1], (double)t);
    }
}

// ---------------- decoder gather + norm + self-loop + bias + ReLU ----------------
// warp per node, lane covers cols [2L, 2L+2)
__global__ void dec_gather_relu_k(const float* __restrict__ m, float* __restrict__ h,
                                  const float* __restrict__ bd)
{
    int row = blockIdx.x * (blockDim.x >> 5) + (threadIdx.x >> 5);
    int lane = threadIdx.x & 31;
    if (row >= Nn) return;
    int dg = min(g_degD[row], CAP);
    const int* pp = &g_dpermv[row * CAP];
    float dn = g_dis[row];
    float a0 = 0.f, a1 = 0.f;
    for (int i = 0; i < dg; i++) {
        int s = pp[i];
        float ds = g_dis[s];
        float2 v = *(const float2*)&m[(size_t)s * 64 + lane * 2];
        a0 += v.x * ds; a1 += v.y * ds;
    }
    float2 ms = *(const float2*)&m[(size_t)row * 64 + lane * 2];
    float2 bv = *(const float2*)&bd[lane * 2];
    float2 o;
    o.x = fmaxf(dn * a0 + ms.x * dn * dn + bv.x, 0.f);
    o.y = fmaxf(dn * a1 + ms.y * dn * dn + bv.y, 0.f);
    *(float2*)&h[(size_t)row * 64 + lane * 2] = o;
}

// ---------------- edge MLP via warp-level bf16 mma.sync (HMMA) ----------------
#define ASTR 528
#define EB_OFF 0
#define EA_OFF (64 * ASTR)
#define E_SMEM (EA_OFF + 64 * ASTR)

__global__ void __launch_bounds__(128)
edge_hmma_k(const float* __restrict__ Wa, const float* __restrict__ ba,
            const float* __restrict__ Wb, const float* __restrict__ bb,
            const int* __restrict__ ps, const int* __restrict__ pd,
            const int* __restrict__ nu, const int* __restrict__ nv,
            const float* __restrict__ tau)
{
    extern __shared__ __align__(16) char smem[];
    uint32 sbase = smem_u32(smem);
    int tid = threadIdx.x;
    int warp = tid >> 5, lane = tid & 31;

    for (int idx = tid; idx < 64 * 256; idx += 128) {
        int n = idx & 63, k = idx >> 6;
        *(__nv_bfloat16*)(smem + EB_OFF + n * ASTR + k * 2) =
            __float2bfloat16(Wa[k * 64 + n]);
    }

    float wbv[16], bav[16];
    #pragma unroll
    for (int nt = 0; nt < 8; nt++) {
        #pragma unroll
        for (int j = 0; j < 2; j++) {
            int col = nt * 8 + (lane & 3) * 2 + j;
            wbv[nt * 2 + j] = Wb[col];
            bav[nt * 2 + j] = ba[col];
        }
    }
    float inv_tau = 1.0f / fmaxf(tau[0], 1e-4f);
    float bb0 = bb[0];
    double lsum = 0.0;
    __syncthreads();

    int R = warp * 16;
    uint32 a_addr = sbase + EA_OFF + (uint32)(R + (lane & 15)) * ASTR + ((lane >> 4) & 1) * 16;
    uint32 b_base = sbase + EB_OFF + (uint32)(((lane >> 4) & 1) * 8 + (lane & 7)) * ASTR
                    + ((lane >> 3) & 1) * 16;

    for (int t = blockIdx.x; t < NT64; t += gridDim.x) {
        {
            int r = tid >> 1, h = tid & 1;
            int e = t * 64 + r;
            int u, v;
            if (e < EP) { u = ps[e]; v = pd[e]; }
            else        { u = nu[e - EP]; v = nv[e - EP]; }
            const float4* pu = (const float4*)&g_hB[(size_t)u * 64 + h * 32];
            const float4* pv = (const float4*)&g_hB[(size_t)v * 64 + h * 32];
            char* arow = smem + EA_OFF + r * ASTR + h * 64;
            #pragma unroll
            for (int i = 0; i < 8; i++) {
                float4 a = pu[i], b = pv[i];
                uint32 hu0 = bfp2(a.x, a.y), hu1 = bfp2(a.z, a.w);
                uint32 hv0 = bfp2(b.x, b.y), hv1 = bfp2(b.z, b.w);
                uint32 dd0 = bfp2(fabsf(a.x - b.x), fabsf(a.y - b.y));
                uint32 dd1 = bfp2(fabsf(a.z - b.z), fabsf(a.w - b.w));
                uint32 pp0 = bfp2(a.x * b.x, a.y * b.y);
                uint32 pp1 = bfp2(a.z * b.z, a.w * b.w);
                *(uint2*)(arow + 0 * 128 + i * 8) = make_uint2(hu0, hu1);
                *(uint2*)(arow + 1 * 128 + i * 8) = make_uint2(hv0, hv1);
                *(uint2*)(arow + 2 * 128 + i * 8) = make_uint2(dd0, dd1);
                *(uint2*)(arow + 3 * 128 + i * 8) = make_uint2(pp0, pp1);
            }
        }
        __syncwarp();

        float acc[8][4];
        #pragma unroll
        for (int n = 0; n < 8; n++)
            #pragma unroll
            for (int j = 0; j < 4; j++) acc[n][j] = 0.f;

        #pragma unroll 4
        for (int kk = 0; kk < 16; kk++) {
            uint32 a[4];
            ldsm4(a, a_addr + kk * 32);
            #pragma unroll
            for (int p = 0; p < 4; p++) {
                uint32 b[4];
                ldsm4(b, b_base + (uint32)(p * 16) * ASTR + kk * 32);
                mma16816(acc[2 * p],     a, b[0], b[1]);
                mma16816(acc[2 * p + 1], a, b[2], b[3]);
            }
        }
        __syncwarp();

        float s0 = 0.f, s1 = 0.f;
        #pragma unroll
        for (int nt = 0; nt < 8; nt++) {
            #pragma unroll
            for (int j = 0; j < 2; j++) {
                float w = wbv[nt * 2 + j], bv = bav[nt * 2 + j];
                s0 += fmaxf(acc[nt][j] + bv, 0.f) * w;
                s1 += fmaxf(acc[nt][2 + j] + bv, 0.f) * w;
            }
        }
        s0 += __shfl_xor_sync(0xffffffffu, s0, 1);
        s0 += __shfl_xor_sync(0xffffffffu, s0, 2);
        s1 += __shfl_xor_sync(0xffffffffu, s1, 1);
        s1 += __shfl_xor_sync(0xffffffffu, s1, 2);
        if ((lane & 3) == 0) {
            int e0 = t * 64 + R + (lane >> 2);
            float logit0 = (s0 + bb0) * inv_tau;
            float x0 = (e0 < EP) ? logit0 : -logit0;
            float ls0 = fminf(x0, 0.f) - log1pf(expf(-fabsf(x0)));
            lsum += (e0 < EP) ? 5.0 * (double)ls0 : (double)ls0;
            int e1 = e0 + 8;
            float logit1 = (s1 + bb0) * inv_tau;
            float x1 = (e1 < EP) ? logit1 : -logit1;
            float ls1 = fminf(x1, 0.f) - log1pf(expf(-fabsf(x1)));
            lsum += (e1 < EP) ? 5.0 * (double)ls1 : (double)ls1;
        }
        __syncwarp();
    }

    #pragma unroll
    for (int o = 16; o; o >>= 1) lsum += __shfl_xor_sync(0xffffffffu, lsum, o);
    if (lane == 0) atomicAdd(&g_acc[0], lsum);
}

// ---------------- finalize ----------------
__global__ void fin_k(float* out) {
    float recon = -(float)(g_acc[0] / (double)ET);
    float kl = -0.5f * (float)(g_acc[1] / (double)(Nn * ZD));
    out[0] = recon + kl;
    out[1] = recon;
    out[2] = kl;
}

// ---------------- launch ----------------
extern "C" void kernel_launch(void* const* d_in, const int* in_sizes, int n_in,
                              void* d_out, int out_size)
{
    const float* x    = (const float*)d_in[0];
    const float* eps  = (const float*)d_in[1];
    const int* eidx   = (const int*)d_in[2];
    const int* pedge  = (const int*)d_in[3];
    const int* nedge  = (const int*)d_in[4];
    const float* W1   = (const float*)d_in[5];
    const float* b1   = (const float*)d_in[6];
    const float* g1   = (const float*)d_in[7];
    const float* bt1  = (const float*)d_in[8];
    const float* Wmu  = (const float*)d_in[9];
    const float* bmu  = (const float*)d_in[10];
    const float* Wlv  = (const float*)d_in[11];
    const float* blv  = (const float*)d_in[12];
    const float* Wd1  = (const float*)d_in[13];
    const float* bd1  = (const float*)d_in[14];
    const float* Wd2  = (const float*)d_in[15];
    const float* bd2  = (const float*)d_in[16];
    const float* Wa   = (const float*)d_in[17];
    const float* ba   = (const float*)d_in[18];
    const float* Wb   = (const float*)d_in[19];
    const float* bb   = (const float*)d_in[20];
    const float* tau  = (const float*)d_in[21];

    const int* src = eidx;
    const int* dst = eidx + E2;
    const int* ps  = pedge;
    const int* pd  = pedge + EP;
    const int* nu  = nedge;
    const int* nv  = nedge + EN;

    float *p_m1, *p_h1, *p_mlv, *p_z, *p_dm, *p_hA, *p_hB;
    int *p_eperm, *p_dperm, *p_degE, *p_degD;
    cudaGetSymbolAddress((void**)&p_m1, g_m1);
    cudaGetSymbolAddress((void**)&p_h1, g_h1);
    cudaGetSymbolAddress((void**)&p_mlv, g_mlv);
    cudaGetSymbolAddress((void**)&p_z, g_z);
    cudaGetSymbolAddress((void**)&p_dm, g_dm);
    cudaGetSymbolAddress((void**)&p_hA, g_hA);
    cudaGetSymbolAddress((void**)&p_hB, g_hB);
    cudaGetSymbolAddress((void**)&p_eperm, g_epermv);
    cudaGetSymbolAddress((void**)&p_dperm, g_dpermv);
    cudaGetSymbolAddress((void**)&p_degE, g_degE);
    cudaGetSymbolAddress((void**)&p_degD, g_degD);

    cudaFuncSetAttribute(edge_hmma_k, cudaFuncAttributeMaxDynamicSharedMemorySize, E_SMEM);

    zero_k<<<(Nn + 255) / 256, 256>>>();
    fill_k<<<(E2 + 255) / 256, 256>>>(src, dst, E2, p_eperm, p_degE);
    fill_k<<<(EP + 255) / 256, 256>>>(ps, pd, EP, p_dperm, p_degD);
    dis_k<<<(Nn + 255) / 256, 256>>>();

    // encoder: m1 = x @ W1
    gemm_k<<<dim3(4, 313), 256>>>(x, W1, p_m1, Nn, 256, 256, 256, 256, 256);
    // h1 = relu(LN(gather(m1) + b1))
    enc_gather_ln_k<<<2500, 256>>>(b1, g1, bt1);

    // mu/lv pre-gather GEMMs into [mu|lv] buffer
    gemm_k<<<dim3(1, 313), 256>>>(p_h1, Wmu, p_mlv,      Nn, 64, 256, 256, 64, 128);
    gemm_k<<<dim3(1, 313), 256>>>(p_h1, Wlv, p_mlv + 64, Nn, 64, 256, 256, 64, 128);
    // gather + bias + z + KL
    mulv_gather_zkl_k<<<2500, 256>>>(eps, bmu, blv);

    // decoder pass 1
    gemm_k<<<dim3(1, 313), 256>>>(p_z, Wd1, p_dm, Nn, 64, 64, 64, 64, 64);
    dec_gather_relu_k<<<2500, 256>>>(p_dm, p_hA, bd1);

    // decoder pass 2
    gemm_k<<<dim3(1, 313), 256>>>(p_hA, Wd2, p_dm, Nn, 64, 64, 64, 64, 64);
    dec_gather_relu_k<<<2500, 256>>>(p_dm, p_hB, bd2);

    // fused edge MLP + weighted BCE on HMMA tensor path
    edge_hmma_k<<<592, 128, E_SMEM>>>(Wa, ba, Wb, bb, ps, pd, nu, nv, tau);

    fin_k<<<1, 1>>>((float*)d_out);
}

// round 12
// speedup vs baseline: 1.3159x; 1.3159x over previous
#include <cuda_runtime.h>
#include <cuda_bf16.h>
#include <math.h>

#define Nn 20000
#define HID 256
#define ZD 64
#define E2 240000     // directed encoder edges (2E)
#define EP 120000     // positive edges
#define EN 600000     // negative edges
#define ET 720000     // EP+EN
#define NT64 (ET / 64)     // 11250 tiles of 64 edges

typedef unsigned long long ull;
typedef unsigned int uint32;

// ---------------- helpers ----------------
__device__ __forceinline__ ull splat2(float v) {
    ull r; asm("mov.b64 %0, {%1, %1};" : "=l"(r) : "f"(v)); return r;
}
__device__ __forceinline__ ull fma2(ull a, ull b, ull c) {
    ull d; asm("fma.rn.f32x2 %0, %1, %2, %3;" : "=l"(d) : "l"(a), "l"(b), "l"(c)); return d;
}
__device__ __forceinline__ float2 unpack2(ull v) {
    float2 f; asm("mov.b64 {%0, %1}, %2;" : "=f"(f.x), "=f"(f.y) : "l"(v)); return f;
}
__device__ __forceinline__ void red_add_v4(float* p, float a, float b, float c, float d) {
    asm volatile("red.global.add.v4.f32 [%0], {%1, %2, %3, %4};"
                 :: "l"(p), "f"(a), "f"(b), "f"(c), "f"(d) : "memory");
}
__device__ __forceinline__ uint32 bfp2(float lo, float hi) {
    uint32 r; asm("cvt.rn.bf16x2.f32 %0, %1, %2;" : "=r"(r) : "f"(hi), "f"(lo)); return r;
}
__device__ __forceinline__ uint32 smem_u32(const void* p) {
    uint32 a; asm("{ .reg .u64 t; cvta.to.shared.u64 t, %1; cvt.u32.u64 %0, t; }" : "=r"(a) : "l"(p));
    return a;
}
__device__ __forceinline__ void ldsm4(uint32* r, uint32 addr) {
    asm volatile("ldmatrix.sync.aligned.m8n8.x4.shared.b16 {%0,%1,%2,%3}, [%4];"
        : "=r"(r[0]), "=r"(r[1]), "=r"(r[2]), "=r"(r[3]) : "r"(addr));
}
__device__ __forceinline__ void mma16816(float* c, const uint32* a, uint32 b0, uint32 b1) {
    asm volatile("mma.sync.aligned.m16n8k16.row.col.f32.bf16.bf16.f32 "
        "{%0,%1,%2,%3}, {%4,%5,%6,%7}, {%8,%9}, {%0,%1,%2,%3};"
        : "+f"(c[0]), "+f"(c[1]), "+f"(c[2]), "+f"(c[3])
        : "r"(a[0]), "r"(a[1]), "r"(a[2]), "r"(a[3]), "r"(b0), "r"(b1));
}

// ---------------- scratch ----------------
__device__ float g_m1[Nn * HID];        // x@W1, then reused as h1
__device__ float g_agg1[Nn * HID];      // encoder scatter target
__device__ float g_mlv[Nn * 128];       // [mu_m | lv_m] pre-scatter
__device__ float g_mulv[Nn * 128];      // aggregated mu|lv
__device__ float g_z[Nn * ZD];
__device__ float g_dm[Nn * ZD];
__device__ float g_hA[Nn * ZD];
__device__ float g_hB[Nn * ZD];
__device__ float g_dis[Nn];
__device__ int   g_deg[Nn];
__device__ double g_acc[2];

// ---------------- dummy (profiler slot alignment) ----------------
__global__ void dummy_k() { }

// ---------------- zero/init ----------------
__global__ void zero_k() {
    size_t i = (size_t)blockIdx.x * blockDim.x + threadIdx.x;
    size_t stride = (size_t)gridDim.x * blockDim.x;
    for (size_t t = i; t < (size_t)Nn * HID; t += stride) g_agg1[t] = 0.f;
    for (size_t t = i; t < (size_t)Nn * 128; t += stride) g_mulv[t] = 0.f;
    for (size_t t = i; t < (size_t)Nn * ZD; t += stride) { g_hA[t] = 0.f; g_hB[t] = 0.f; }
    for (size_t t = i; t < (size_t)Nn; t += stride) g_deg[t] = 0;
    if (i < 2) g_acc[i] = 0.0;
}

// ---------------- tiled fp32 GEMM with FFMA2 ----------------
__global__ void gemm_k(const float* __restrict__ A, const float* __restrict__ B,
                       float* __restrict__ C, int M, int Ncols, int K,
                       int lda, int ldb, int ldc)
{
    __shared__ float As[16][64];
    __shared__ float Bs[16][64];
    int tid = threadIdx.x;
    int tx = tid & 15, ty = tid >> 4;
    int bm0 = blockIdx.y * 64, bn0 = blockIdx.x * 64;

    ull pacc[4][2];
    #pragma unroll
    for (int i = 0; i < 4; i++) { pacc[i][0] = 0ull; pacc[i][1] = 0ull; }

    for (int k0 = 0; k0 < K; k0 += 16) {
        {
            int r = tid >> 2, kk = (tid & 3) << 2;
            float4 v = make_float4(0.f, 0.f, 0.f, 0.f);
            if (bm0 + r < M)
                v = *(const float4*)(A + (size_t)(bm0 + r) * lda + k0 + kk);
            As[kk + 0][r] = v.x; As[kk + 1][r] = v.y;
            As[kk + 2][r] = v.z; As[kk + 3][r] = v.w;
        }
        {
            int kk = tid >> 4, c = (tid & 15) << 2;
            float4 v = *(const float4*)(B + (size_t)(k0 + kk) * ldb + bn0 + c);
            *(float4*)&Bs[kk][c] = v;
        }
        __syncthreads();
        #pragma unroll
        for (int kk = 0; kk < 16; kk++) {
            float4 a = *(const float4*)&As[kk][ty * 4];
            const ull* bp = (const ull*)&Bs[kk][tx * 4];
            ull b01 = bp[0], b23 = bp[1];
            float av[4] = {a.x, a.y, a.z, a.w};
            #pragma unroll
            for (int i = 0; i < 4; i++) {
                ull as = splat2(av[i]);
                pacc[i][0] = fma2(b01, as, pacc[i][0]);
                pacc[i][1] = fma2(b23, as, pacc[i][1]);
            }
        }
        __syncthreads();
    }
    #pragma unroll
    for (int i = 0; i < 4; i++) {
        int row = bm0 + ty * 4 + i;
        if (row < M) {
            float2 lo = unpack2(pacc[i][0]);
            float2 hi = unpack2(pacc[i][1]);
            *(float4*)(C + (size_t)row * ldc + bn0 + tx * 4) =
                make_float4(lo.x, lo.y, hi.x, hi.y);
        }
    }
}

// ---------------- scatter-add (REDG.128) ----------------
__global__ void scatter_add_k(const float* __restrict__ m, float* __restrict__ out,
                              const int* __restrict__ src, const int* __restrict__ dst,
                              int nmsg, int W4)
{
    int idx = blockIdx.x * blockDim.x + threadIdx.x;
    int total = nmsg * W4;
    if (idx >= total) return;
    int e = idx / W4, c = idx - e * W4;
    int s = src[e], d = dst[e];
    float4 v = ((const float4*)m)[(size_t)s * W4 + c];
    float* o = out + ((size_t)d * W4 + c) * 4;
    red_add_v4(o, v.x, v.y, v.z, v.w);
}

// ---------------- LayerNorm + ReLU ----------------
__global__ void ln_relu_k(const float* __restrict__ b1, const float* __restrict__ g1,
                          const float* __restrict__ bt1)
{
    int row = blockIdx.x * (blockDim.x >> 5) + (threadIdx.x >> 5);
    int lane = threadIdx.x & 31;
    if (row >= Nn) return;
    const float* in = g_agg1 + (size_t)row * 256;
    float v[8];
    float s = 0.f;
    #pragma unroll
    for (int i = 0; i < 8; i++) { v[i] = in[i * 32 + lane] + b1[i * 32 + lane]; s += v[i]; }
    #pragma unroll
    for (int o = 16; o; o >>= 1) s += __shfl_xor_sync(0xffffffffu, s, o);
    float mu = s * (1.0f / 256.0f);
    float vs = 0.f;
    #pragma unroll
    for (int i = 0; i < 8; i++) { float d = v[i] - mu; vs += d * d; }
    #pragma unroll
    for (int o = 16; o; o >>= 1) vs += __shfl_xor_sync(0xffffffffu, vs, o);
    float rs = rsqrtf(vs * (1.0f / 256.0f) + 1e-5f);
    float* outp = g_m1 + (size_t)row * 256;
    #pragma unroll
    for (int i = 0; i < 8; i++) {
        int c = i * 32 + lane;
        outp[c] = fmaxf((v[i] - mu) * rs * g1[c] + bt1[c], 0.f);
    }
}

// ---------------- z + KL ----------------
__global__ void z_kl_k(const float* __restrict__ eps, const float* __restrict__ bmu,
                       const float* __restrict__ blv)
{
    __shared__ float red[256];
    int idx = blockIdx.x * 256 + threadIdx.x;
    float t = 0.f;
    if (idx < Nn * ZD) {
        int n = idx >> 6, j = idx & 63;
        float mu = g_mulv[(size_t)n * 128 + j] + bmu[j];
        float lv = g_mulv[(size_t)n * 128 + 64 + j] + blv[j];
        g_z[idx] = mu + eps[idx] * expf(0.5f * lv);
        t = 1.0f + lv - mu * mu - expf(lv);
    }
    red[threadIdx.x] = t;
    __syncthreads();
    for (int s = 128; s; s >>= 1) {
        if (threadIdx.x < s) red[threadIdx.x] += red[threadIdx.x + s];
        __syncthreads();
    }
    if (threadIdx.x == 0) atomicAdd(&g_acc[1], (double)red[0]);
}

// ---------------- decoder degree / norm ----------------
__global__ void deg_k(const int* __restrict__ pd) {
    int e = blockIdx.x * blockDim.x + threadIdx.x;
    if (e < EP) atomicAdd(&g_deg[pd[e]], 1);
}
__global__ void dis_k() {
    int n = blockIdx.x * blockDim.x + threadIdx.x;
    if (n < Nn) g_dis[n] = rsqrtf((float)g_deg[n] + 1.0f);
}

__global__ void scat_norm_k(const float* __restrict__ m, float* __restrict__ out,
                            const int* __restrict__ ps, const int* __restrict__ pd)
{
    int idx = blockIdx.x * blockDim.x + threadIdx.x;
    if (idx >= EP * 16) return;
    int e = idx >> 4, c = idx & 15;
    int s = ps[e], d = pd[e];
    float nrm = g_dis[s] * g_dis[d];
    float4 v = ((const float4*)m)[(size_t)s * 16 + c];
    float* o = out + ((size_t)d * 16 + c) * 4;
    red_add_v4(o, v.x * nrm, v.y * nrm, v.z * nrm, v.w * nrm);
}

__global__ void relu_dec_k(const float* __restrict__ m, float* __restrict__ h,
                           const float* __restrict__ bd)
{
    int idx = blockIdx.x * blockDim.x + threadIdx.x;
    if (idx >= Nn * ZD) return;
    int n = idx >> 6, j = idx & 63;
    float dn = g_dis[n];
    h[idx] = fmaxf(h[idx] + m[idx] * dn * dn + bd[j], 0.f);
}

// ---------------- edge MLP via warp-level bf16 mma.sync (HMMA) ----------------
#define ASTR 528
#define EB_OFF 0
#define EA_OFF (64 * ASTR)
#define E_SMEM (EA_OFF + 64 * ASTR)

__global__ void __launch_bounds__(128)
edge_hmma_k(const float* __restrict__ Wa, const float* __restrict__ ba,
            const float* __restrict__ Wb, const float* __restrict__ bb,
            const int* __restrict__ ps, const int* __restrict__ pd,
            const int* __restrict__ nu, const int* __restrict__ nv,
            const float* __restrict__ tau)
{
    extern __shared__ __align__(16) char smem[];
    uint32 sbase = smem_u32(smem);
    int tid = threadIdx.x;
    int warp = tid >> 5, lane = tid & 31;

    for (int idx = tid; idx < 64 * 256; idx += 128) {
        int n = idx & 63, k = idx >> 6;
        *(__nv_bfloat16*)(smem + EB_OFF + n * ASTR + k * 2) =
            __float2bfloat16(Wa[k * 64 + n]);
    }

    float wbv[16], bav[16];
    #pragma unroll
    for (int nt = 0; nt < 8; nt++) {
        #pragma unroll
        for (int j = 0; j < 2; j++) {
            int col = nt * 8 + (lane & 3) * 2 + j;
            wbv[nt * 2 + j] = Wb[col];
            bav[nt * 2 + j] = ba[col];
        }
    }
    float inv_tau = 1.0f / fmaxf(tau[0], 1e-4f);
    float bb0 = bb[0];
    double lsum = 0.0;
    __syncthreads();

    int R = warp * 16;
    uint32 a_addr = sbase + EA_OFF + (uint32)(R + (lane & 15)) * ASTR + ((lane >> 4) & 1) * 16;
    uint32 b_base = sbase + EB_OFF + (uint32)(((lane >> 4) & 1) * 8 + (lane & 7)) * ASTR
                    + ((lane >> 3) & 1) * 16;

    for (int t = blockIdx.x; t < NT64; t += gridDim.x) {
        {
            int r = tid >> 1, h = tid & 1;
            int e = t * 64 + r;
            int u, v;
            if (e < EP) { u = ps[e]; v = pd[e]; }
            else        { u = nu[e - EP]; v = nv[e - EP]; }
            const float4* pu = (const float4*)&g_hB[(size_t)u * 64 + h * 32];
            const float4* pv = (const float4*)&g_hB[(size_t)v * 64 + h * 32];
            char* arow = smem + EA_OFF + r * ASTR + h * 64;
            #pragma unroll
            for (int i = 0; i < 8; i++) {
                float4 a = pu[i], b = pv[i];
                uint32 hu0 = bfp2(a.x, a.y), hu1 = bfp2(a.z, a.w);
                uint32 hv0 = bfp2(b.x, b.y), hv1 = bfp2(b.z, b.w);
                uint32 dd0 = bfp2(fabsf(a.x - b.x), fabsf(a.y - b.y));
                uint32 dd1 = bfp2(fabsf(a.z - b.z), fabsf(a.w - b.w));
                uint32 pp0 = bfp2(a.x * b.x, a.y * b.y);
                uint32 pp1 = bfp2(a.z * b.z, a.w * b.w);
                *(uint2*)(arow + 0 * 128 + i * 8) = make_uint2(hu0, hu1);
                *(uint2*)(arow + 1 * 128 + i * 8) = make_uint2(hv0, hv1);
                *(uint2*)(arow + 2 * 128 + i * 8) = make_uint2(dd0, dd1);
                *(uint2*)(arow + 3 * 128 + i * 8) = make_uint2(pp0, pp1);
            }
        }
        __syncwarp();

        float acc[8][4];
        #pragma unroll
        for (int n = 0; n < 8; n++)
            #pragma unroll
            for (int j = 0; j < 4; j++) acc[n][j] = 0.f;

        #pragma unroll 4
        for (int kk = 0; kk < 16; kk++) {
            uint32 a[4];
            ldsm4(a, a_addr + kk * 32);
            #pragma unroll
            for (int p = 0; p < 4; p++) {
                uint32 b[4];
                ldsm4(b, b_base + (uint32)(p * 16) * ASTR + kk * 32);
                mma16816(acc[2 * p],     a, b[0], b[1]);
                mma16816(acc[2 * p + 1], a, b[2], b[3]);
            }
        }
        __syncwarp();

        float s0 = 0.f, s1 = 0.f;
        #pragma unroll
        for (int nt = 0; nt < 8; nt++) {
            #pragma unroll
            for (int j = 0; j < 2; j++) {
                float w = wbv[nt * 2 + j], bv = bav[nt * 2 + j];
                s0 += fmaxf(acc[nt][j] + bv, 0.f) * w;
                s1 += fmaxf(acc[nt][2 + j] + bv, 0.f) * w;
            }
        }
        s0 += __shfl_xor_sync(0xffffffffu, s0, 1);
        s0 += __shfl_xor_sync(0xffffffffu, s0, 2);
        s1 += __shfl_xor_sync(0xffffffffu, s1, 1);
        s1 += __shfl_xor_sync(0xffffffffu, s1, 2);
        if ((lane & 3) == 0) {
            int e0 = t * 64 + R + (lane >> 2);
            float logit0 = (s0 + bb0) * inv_tau;
            float x0 = (e0 < EP) ? logit0 : -logit0;
            float ls0 = fminf(x0, 0.f) - log1pf(expf(-fabsf(x0)));
            lsum += (e0 < EP) ? 5.0 * (double)ls0 : (double)ls0;
            int e1 = e0 + 8;
            float logit1 = (s1 + bb0) * inv_tau;
            float x1 = (e1 < EP) ? logit1 : -logit1;
            float ls1 = fminf(x1, 0.f) - log1pf(expf(-fabsf(x1)));
            lsum += (e1 < EP) ? 5.0 * (double)ls1 : (double)ls1;
        }
        __syncwarp();
    }

    #pragma unroll
    for (int o = 16; o; o >>= 1) lsum += __shfl_xor_sync(0xffffffffu, lsum, o);
    if (lane == 0) atomicAdd(&g_acc[0], lsum);
}

// ---------------- finalize ----------------
__global__ void fin_k(float* out) {
    float recon = -(float)(g_acc[0] / (double)ET);
    float kl = -0.5f * (float)(g_acc[1] / (double)(Nn * ZD));
    out[0] = recon + kl;
    out[1] = recon;
    out[2] = kl;
}

// ---------------- launch ----------------
extern "C" void kernel_launch(void* const* d_in, const int* in_sizes, int n_in,
                              void* d_out, int out_size)
{
    const float* x    = (const float*)d_in[0];
    const float* eps  = (const float*)d_in[1];
    const int* eidx   = (const int*)d_in[2];
    const int* pedge  = (const int*)d_in[3];
    const int* nedge  = (const int*)d_in[4];
    const float* W1   = (const float*)d_in[5];
    const float* b1   = (const float*)d_in[6];
    const float* g1   = (const float*)d_in[7];
    const float* bt1  = (const float*)d_in[8];
    const float* Wmu  = (const float*)d_in[9];
    const float* bmu  = (const float*)d_in[10];
    const float* Wlv  = (const float*)d_in[11];
    const float* blv  = (const float*)d_in[12];
    const float* Wd1  = (const float*)d_in[13];
    const float* bd1  = (const float*)d_in[14];
    const float* Wd2  = (const float*)d_in[15];
    const float* bd2  = (const float*)d_in[16];
    const float* Wa   = (const float*)d_in[17];
    const float* ba   = (const float*)d_in[18];
    const float* Wb   = (const float*)d_in[19];
    const float* bb   = (const float*)d_in[20];
    const float* tau  = (const float*)d_in[21];

    const int* src = eidx;
    const int* dst = eidx + E2;
    const int* ps  = pedge;
    const int* pd  = pedge + EP;
    const int* nu  = nedge;
    const int* nv  = nedge + EN;

    float *p_m1, *p_mlv, *p_mulv, *p_z, *p_dm, *p_hA, *p_hB, *p_agg1;
    cudaGetSymbolAddress((void**)&p_m1, g_m1);
    cudaGetSymbolAddress((void**)&p_agg1, g_agg1);
    cudaGetSymbolAddress((void**)&p_mlv, g_mlv);
    cudaGetSymbolAddress((void**)&p_mulv, g_mulv);
    cudaGetSymbolAddress((void**)&p_z, g_z);
    cudaGetSymbolAddress((void**)&p_dm, g_dm);
    cudaGetSymbolAddress((void**)&p_hA, g_hA);
    cudaGetSymbolAddress((void**)&p_hB, g_hB);

    cudaFuncSetAttribute(edge_hmma_k, cudaFuncAttributeMaxDynamicSharedMemorySize, E_SMEM);

    // launch-slot alignment: profiler captures the 4th launch -> make it scatter_add_k
    dummy_k<<<1, 32>>>();

    zero_k<<<2048, 256>>>();

    // encoder: m1 = x @ W1 (fp32 FFMA2)
    gemm_k<<<dim3(4, 313), 256>>>(x, W1, p_m1, Nn, 256, 256, 256, 256, 256);
    // 4th launch: the 64-wide encoder scatter (profiling target)
    scatter_add_k<<<(E2 * 64 + 255) / 256, 256>>>(p_m1, p_agg1, src, dst, E2, 64);
    ln_relu_k<<<2500, 256>>>(b1, g1, bt1);

    // mu/lv pre-scatter GEMMs (fp32) into [mu|lv] buffer
    gemm_k<<<dim3(1, 313), 256>>>(p_m1, Wmu, p_mlv,      Nn, 64, 256, 256, 64, 128);
    gemm_k<<<dim3(1, 313), 256>>>(p_m1, Wlv, p_mlv + 64, Nn, 64, 256, 256, 64, 128);
    scatter_add_k<<<(E2 * 32 + 255) / 256, 256>>>(p_mlv, p_mulv, src, dst, E2, 32);

    z_kl_k<<<5000, 256>>>(eps, bmu, blv);

    deg_k<<<(EP + 255) / 256, 256>>>(pd);
    dis_k<<<(Nn + 255) / 256, 256>>>();

    // decoder pass 1
    gemm_k<<<dim3(1, 313), 256>>>(p_z, Wd1, p_dm, Nn, 64, 64, 64, 64, 64);
    scat_norm_k<<<(EP * 16 + 255) / 256, 256>>>(p_dm, p_hA, ps, pd);
    relu_dec_k<<<(Nn * 64 + 255) / 256, 256>>>(p_dm, p_hA, bd1);

    // decoder pass 2
    gemm_k<<<dim3(1, 313), 256>>>(p_hA, Wd2, p_dm, Nn, 64, 64, 64, 64, 64);
    scat_norm_k<<<(EP * 16 + 255) / 256, 256>>>(p_dm, p_hB, ps, pd);
    relu_dec_k<<<(Nn * 64 + 255) / 256, 256>>>(p_dm, p_hB, bd2);

    // fused edge MLP + weighted BCE on HMMA tensor path
    edge_hmma_k<<<592, 128, E_SMEM>>>(Wa, ba, Wb, bb, ps, pd, nu, nv, tau);

    fin_k<<<1, 1>>>((float*)d_out);
}